// round 2
// baseline (speedup 1.0000x reference)
#include <cuda_runtime.h>
#include <cuda_bf16.h>
#include <cstdint>

#define D 128
#define NMAX 50000
#define D4 (D/4)   // 32 float4 per row

// ---------------- scratch (no allocations allowed) ----------------
__device__ int   g_deg[NMAX];
__device__ float g_dinv[NMAX];
__device__ float g_h[(size_t)NMAX * D];   // linear-transform output
__device__ float g_a[(size_t)NMAX * D];   // aggregation buffer (layer 1)
__device__ int   g_is64;                  // 1 if edge_index is int64, 0 if int32

// ---------------- edge_index dtype detection ----------------
// If edge_index is int64 (values < 2^31), every odd 32-bit word is 0.
// For random int32 indices in [0, 50000), 64 consecutive odd words all being
// zero has probability ~ (1/50000)^64 ~ 0. One thread, deterministic.
__global__ void k_detect(const int* __restrict__ ei) {
    if (blockIdx.x == 0 && threadIdx.x == 0) {
        int all0 = 1;
        for (int i = 0; i < 64; ++i)
            if (ei[2 * i + 1] != 0) { all0 = 0; break; }
        g_is64 = all0;
    }
}

__device__ __forceinline__ int load_idx(const int* __restrict__ ei, size_t pos) {
    // little-endian: low word of int64 element i sits at int32 offset 2*i
    return g_is64 ? ei[2 * pos] : ei[pos];
}

// ---------------- degree / normalization ----------------
__global__ void k_init_deg(int n) {
    int i = blockIdx.x * blockDim.x + threadIdx.x;
    if (i < n) g_deg[i] = 1;              // self-loop contributes 1
}

__global__ void k_count(const int* __restrict__ ei, int E) {
    int e = blockIdx.x * blockDim.x + threadIdx.x;
    if (e < E) {
        int d = load_idx(ei, (size_t)E + e);
        atomicAdd(&g_deg[d], 1);
    }
}

__global__ void k_dinv(int n) {
    int i = blockIdx.x * blockDim.x + threadIdx.x;
    if (i < n) g_dinv[i] = rsqrtf((float)g_deg[i]);
}

// ---------------- zero a float buffer (float4 granularity) ----------------
__global__ void k_zero(float* __restrict__ p, int n4) {
    int i = blockIdx.x * blockDim.x + threadIdx.x;
    if (i < n4) ((float4*)p)[i] = make_float4(0.f, 0.f, 0.f, 0.f);
}

// ---------------- GEMM: C[M,128] = A[M,128] @ W[128,128] ----------------
// Block = 256 threads covers 32 rows x 128 cols.
//   lane (tid&31)  -> 4 consecutive output cols (float4)
//   rs   (tid>>5)  -> 4 consecutive rows
#define FMA4(acc, s, b) { acc.x = fmaf(s, b.x, acc.x); acc.y = fmaf(s, b.y, acc.y); \
                          acc.z = fmaf(s, b.z, acc.z); acc.w = fmaf(s, b.w, acc.w); }

__global__ void k_gemm(const float* __restrict__ A, const float* __restrict__ Wm,
                       float* __restrict__ C, int M) {
    int lane = threadIdx.x & 31;
    int rs   = threadIdx.x >> 5;
    int row0 = blockIdx.x * 32 + rs * 4;
    if (row0 >= M) return;               // M % 4 == 0, so 4 rows are all valid

    const float4* A4 = (const float4*)A;
    const float4* W4 = (const float4*)Wm;

    float4 acc0 = make_float4(0,0,0,0), acc1 = acc0, acc2 = acc0, acc3 = acc0;

    size_t ar0 = (size_t)(row0 + 0) * D4;
    size_t ar1 = (size_t)(row0 + 1) * D4;
    size_t ar2 = (size_t)(row0 + 2) * D4;
    size_t ar3 = (size_t)(row0 + 3) * D4;

#pragma unroll 4
    for (int k4 = 0; k4 < D4; ++k4) {
        float4 a0 = A4[ar0 + k4];
        float4 a1 = A4[ar1 + k4];
        float4 a2 = A4[ar2 + k4];
        float4 a3 = A4[ar3 + k4];
        int k = k4 * 4;
        float4 b0 = W4[(size_t)(k + 0) * D4 + lane];
        float4 b1 = W4[(size_t)(k + 1) * D4 + lane];
        float4 b2 = W4[(size_t)(k + 2) * D4 + lane];
        float4 b3 = W4[(size_t)(k + 3) * D4 + lane];

        FMA4(acc0, a0.x, b0); FMA4(acc0, a0.y, b1); FMA4(acc0, a0.z, b2); FMA4(acc0, a0.w, b3);
        FMA4(acc1, a1.x, b0); FMA4(acc1, a1.y, b1); FMA4(acc1, a1.z, b2); FMA4(acc1, a1.w, b3);
        FMA4(acc2, a2.x, b0); FMA4(acc2, a2.y, b1); FMA4(acc2, a2.z, b2); FMA4(acc2, a2.w, b3);
        FMA4(acc3, a3.x, b0); FMA4(acc3, a3.y, b1); FMA4(acc3, a3.z, b2); FMA4(acc3, a3.w, b3);
    }

    float4* C4 = (float4*)C;
    C4[ar0 + lane] = acc0;
    C4[ar1 + lane] = acc1;
    C4[ar2 + lane] = acc2;
    C4[ar3 + lane] = acc3;
}

// ---------------- edge aggregation: out[dst] += H[src] * dinv[src]*dinv[dst] ----
// One warp per edge (grid-stride). 128 floats = 1 float4 per lane.
// Scatter-add via red.global.add.v4.f32 (sm_90+): 4x fewer atomic lane-ops.
__global__ void k_aggregate(const int* __restrict__ ei,
                            const float* __restrict__ H,
                            float* __restrict__ out, int E) {
    int warp   = (int)((blockIdx.x * (size_t)blockDim.x + threadIdx.x) >> 5);
    int lane   = threadIdx.x & 31;
    int nwarps = (int)((gridDim.x * (size_t)blockDim.x) >> 5);

    for (int e = warp; e < E; e += nwarps) {
        int s = load_idx(ei, (size_t)e);
        int d = load_idx(ei, (size_t)E + e);
        float nm = g_dinv[s] * g_dinv[d];

        float4 v = ((const float4*)(H + (size_t)s * D))[lane];
        v.x *= nm; v.y *= nm; v.z *= nm; v.w *= nm;

        float* p = out + (size_t)d * D + lane * 4;
        asm volatile("red.global.add.v4.f32 [%0], {%1, %2, %3, %4};"
                     :: "l"(p), "f"(v.x), "f"(v.y), "f"(v.z), "f"(v.w)
                     : "memory");
    }
}

// ---------------- epilogue: out = relu(agg + H*dinv^2 + b) ----------------
__global__ void k_finalize(const float* __restrict__ agg, const float* __restrict__ H,
                           const float* __restrict__ b, float* __restrict__ out, int n) {
    int idx = blockIdx.x * blockDim.x + threadIdx.x;   // over n * 32 float4
    int total = n * D4;
    if (idx >= total) return;
    int node = idx >> 5;    // D4 == 32
    int q    = idx & 31;

    float di = g_dinv[node];
    float sl = di * di;     // self-loop norm

    float4 av = ((const float4*)agg)[idx];
    float4 hv = ((const float4*)H)[idx];
    float4 bv = ((const float4*)b)[q];

    float4 r;
    r.x = fmaxf(fmaf(hv.x, sl, av.x) + bv.x, 0.f);
    r.y = fmaxf(fmaf(hv.y, sl, av.y) + bv.y, 0.f);
    r.z = fmaxf(fmaf(hv.z, sl, av.z) + bv.z, 0.f);
    r.w = fmaxf(fmaf(hv.w, sl, av.w) + bv.w, 0.f);

    ((float4*)out)[idx] = r;
}

// ---------------- launch ----------------
extern "C" void kernel_launch(void* const* d_in, const int* in_sizes, int n_in,
                              void* d_out, int out_size) {
    const float* x  = (const float*)d_in[0];
    const int*   ei = (const int*)d_in[1];     // int32 (JAX x64 off) or int64 (detected)
    const float* W1 = (const float*)d_in[2];
    const float* b1 = (const float*)d_in[3];
    const float* W2 = (const float*)d_in[4];
    const float* b2 = (const float*)d_in[5];
    float* out = (float*)d_out;

    int n = in_sizes[0] / D;        // 50000
    int E = in_sizes[1] / 2;        // 800000

    float *h, *a;
    cudaGetSymbolAddress((void**)&h, g_h);
    cudaGetSymbolAddress((void**)&a, g_a);

    int n4 = n * D4;                // float4 count of an [n,128] buffer

    // dtype detection + normalization
    k_detect<<<1, 32>>>(ei);
    k_init_deg<<<(n + 255) / 256, 256>>>(n);
    k_count<<<(E + 255) / 256, 256>>>(ei, E);
    k_dinv<<<(n + 255) / 256, 256>>>(n);

    // ---- layer 1 ----
    k_gemm<<<(n + 31) / 32, 256>>>(x, W1, h, n);
    k_zero<<<(n4 + 255) / 256, 256>>>(a, n4);
    k_aggregate<<<2048, 256>>>(ei, h, a, E);
    k_finalize<<<(n4 + 255) / 256, 256>>>(a, h, b1, a, n);   // in-place -> a = relu(...)

    // ---- layer 2 ----
    k_gemm<<<(n + 31) / 32, 256>>>(a, W2, h, n);
    k_zero<<<(n4 + 255) / 256, 256>>>(out, n4);
    k_aggregate<<<2048, 256>>>(ei, h, out, E);
    k_finalize<<<(n4 + 255) / 256, 256>>>(out, h, b2, out, n);
}

// round 3
// speedup vs baseline: 1.1074x; 1.1074x over previous
#include <cuda_runtime.h>
#include <cuda_bf16.h>
#include <cstdint>

#define D 128
#define NMAX 50000
#define EMAX 800000
#define D4 (D/4)   // 32 float4 per row

// ---------------- scratch (no allocations allowed) ----------------
__device__ int   g_deg[NMAX];          // 1 + in-degree (self-loop included)
__device__ float g_dinv[NMAX];
__device__ int   g_rowstart[NMAX];     // CSR row offsets (real edges only)
__device__ int   g_cur[NMAX];          // fill cursors
__device__ int   g_esrc[EMAX];         // CSR: src node per slot
__device__ float g_enorm[EMAX];        // CSR: dinv[src]*dinv[dst] per slot
__device__ float g_h[(size_t)NMAX * D];   // linear-transform output
__device__ float g_a[(size_t)NMAX * D];   // layer-1 activation
__device__ int   g_is64;               // 1 if edge_index is int64, 0 if int32

// ---------------- edge_index dtype detection ----------------
__global__ void k_detect(const int* __restrict__ ei) {
    if (blockIdx.x == 0 && threadIdx.x == 0) {
        int all0 = 1;
        for (int i = 0; i < 64; ++i)
            if (ei[2 * i + 1] != 0) { all0 = 0; break; }
        g_is64 = all0;
    }
}

__device__ __forceinline__ int load_idx(const int* __restrict__ ei, size_t pos) {
    return g_is64 ? ei[2 * pos] : ei[pos];
}

// ---------------- degree / normalization ----------------
__global__ void k_init_deg(int n) {
    int i = blockIdx.x * blockDim.x + threadIdx.x;
    if (i < n) g_deg[i] = 1;              // self-loop contributes 1
}

__global__ void k_count(const int* __restrict__ ei, int E) {
    int e = blockIdx.x * blockDim.x + threadIdx.x;
    if (e < E) atomicAdd(&g_deg[load_idx(ei, (size_t)E + e)], 1);
}

__global__ void k_dinv(int n) {
    int i = blockIdx.x * blockDim.x + threadIdx.x;
    if (i < n) g_dinv[i] = rsqrtf((float)g_deg[i]);
}

// ---------------- exclusive scan of (deg-1) -> rowstart; reset cursors ----
// Single block, 1024 threads, each owns a contiguous chunk.
__global__ void k_scan(int n) {
    __shared__ int part[1024];
    const int tid = threadIdx.x;
    const int chunk = (n + 1023) / 1024;
    const int beg = tid * chunk;
    const int end = min(beg + chunk, n);

    int s = 0;
    for (int i = beg; i < end; ++i) s += g_deg[i] - 1;
    part[tid] = s;
    __syncthreads();

    // Hillis-Steele inclusive scan over 1024 partials
    for (int off = 1; off < 1024; off <<= 1) {
        int v = (tid >= off) ? part[tid - off] : 0;
        __syncthreads();
        part[tid] += v;
        __syncthreads();
    }

    int run = (tid > 0) ? part[tid - 1] : 0;   // exclusive offset for this chunk
    for (int i = beg; i < end; ++i) {
        g_rowstart[i] = run;
        g_cur[i] = 0;
        run += g_deg[i] - 1;
    }
}

// ---------------- CSR fill: slot <- (src, norm) grouped by dst ----------------
__global__ void k_fill(const int* __restrict__ ei, int E) {
    int e = blockIdx.x * blockDim.x + threadIdx.x;
    if (e >= E) return;
    int s = load_idx(ei, (size_t)e);
    int d = load_idx(ei, (size_t)E + e);
    int pos = g_rowstart[d] + atomicAdd(&g_cur[d], 1);
    g_esrc[pos]  = s;
    g_enorm[pos] = g_dinv[s] * g_dinv[d];
}

// ---------------- GEMM: C[M,128] = A[M,128] @ W[128,128] ----------------
#define FMA4(acc, s, b) { acc.x = fmaf(s, b.x, acc.x); acc.y = fmaf(s, b.y, acc.y); \
                          acc.z = fmaf(s, b.z, acc.z); acc.w = fmaf(s, b.w, acc.w); }

__global__ void k_gemm(const float* __restrict__ A, const float* __restrict__ Wm,
                       float* __restrict__ C, int M) {
    int lane = threadIdx.x & 31;
    int rs   = threadIdx.x >> 5;
    int row0 = blockIdx.x * 32 + rs * 4;
    if (row0 >= M) return;

    const float4* A4 = (const float4*)A;
    const float4* W4 = (const float4*)Wm;

    float4 acc0 = make_float4(0,0,0,0), acc1 = acc0, acc2 = acc0, acc3 = acc0;

    size_t ar0 = (size_t)(row0 + 0) * D4;
    size_t ar1 = (size_t)(row0 + 1) * D4;
    size_t ar2 = (size_t)(row0 + 2) * D4;
    size_t ar3 = (size_t)(row0 + 3) * D4;

#pragma unroll 4
    for (int k4 = 0; k4 < D4; ++k4) {
        float4 a0 = A4[ar0 + k4];
        float4 a1 = A4[ar1 + k4];
        float4 a2 = A4[ar2 + k4];
        float4 a3 = A4[ar3 + k4];
        int k = k4 * 4;
        float4 b0 = W4[(size_t)(k + 0) * D4 + lane];
        float4 b1 = W4[(size_t)(k + 1) * D4 + lane];
        float4 b2 = W4[(size_t)(k + 2) * D4 + lane];
        float4 b3 = W4[(size_t)(k + 3) * D4 + lane];

        FMA4(acc0, a0.x, b0); FMA4(acc0, a0.y, b1); FMA4(acc0, a0.z, b2); FMA4(acc0, a0.w, b3);
        FMA4(acc1, a1.x, b0); FMA4(acc1, a1.y, b1); FMA4(acc1, a1.z, b2); FMA4(acc1, a1.w, b3);
        FMA4(acc2, a2.x, b0); FMA4(acc2, a2.y, b1); FMA4(acc2, a2.z, b2); FMA4(acc2, a2.w, b3);
        FMA4(acc3, a3.x, b0); FMA4(acc3, a3.y, b1); FMA4(acc3, a3.z, b2); FMA4(acc3, a3.w, b3);
    }

    float4* C4 = (float4*)C;
    C4[ar0 + lane] = acc0;
    C4[ar1 + lane] = acc1;
    C4[ar2 + lane] = acc2;
    C4[ar3 + lane] = acc3;
}

// ---------------- CSR aggregation + self-loop + bias + ReLU --------------
// One warp per dst node. Each lane owns one float4 (4 cols) of the row.
// Register accumulation, single store: no atomics, no separate zero/finalize.
__global__ void k_agg_csr(const float* __restrict__ H,
                          const float* __restrict__ b,
                          float* __restrict__ out, int n) {
    int warp = (int)((blockIdx.x * (size_t)blockDim.x + threadIdx.x) >> 5);
    int lane = threadIdx.x & 31;
    if (warp >= n) return;
    int node = warp;

    const float4* H4 = (const float4*)H;

    float di = g_dinv[node];
    float sl = di * di;

    // self-loop contribution
    float4 acc = H4[(size_t)node * D4 + lane];
    acc.x *= sl; acc.y *= sl; acc.z *= sl; acc.w *= sl;

    int p   = g_rowstart[node];
    int end = p + (g_deg[node] - 1);

    // unroll by 2 for memory-level parallelism
    for (; p + 1 < end; p += 2) {
        int   s0 = g_esrc[p],     s1 = g_esrc[p + 1];
        float n0 = g_enorm[p],    n1 = g_enorm[p + 1];
        float4 v0 = H4[(size_t)s0 * D4 + lane];
        float4 v1 = H4[(size_t)s1 * D4 + lane];
        FMA4(acc, n0, v0);
        FMA4(acc, n1, v1);
    }
    if (p < end) {
        int   s0 = g_esrc[p];
        float n0 = g_enorm[p];
        float4 v0 = H4[(size_t)s0 * D4 + lane];
        FMA4(acc, n0, v0);
    }

    float4 bv = ((const float4*)b)[lane];
    float4 r;
    r.x = fmaxf(acc.x + bv.x, 0.f);
    r.y = fmaxf(acc.y + bv.y, 0.f);
    r.z = fmaxf(acc.z + bv.z, 0.f);
    r.w = fmaxf(acc.w + bv.w, 0.f);
    ((float4*)out)[(size_t)node * D4 + lane] = r;
}

// ---------------- launch ----------------
extern "C" void kernel_launch(void* const* d_in, const int* in_sizes, int n_in,
                              void* d_out, int out_size) {
    const float* x  = (const float*)d_in[0];
    const int*   ei = (const int*)d_in[1];
    const float* W1 = (const float*)d_in[2];
    const float* b1 = (const float*)d_in[3];
    const float* W2 = (const float*)d_in[4];
    const float* b2 = (const float*)d_in[5];
    float* out = (float*)d_out;

    int n = in_sizes[0] / D;        // 50000
    int E = in_sizes[1] / 2;        // 800000

    float *h, *a;
    cudaGetSymbolAddress((void**)&h, g_h);
    cudaGetSymbolAddress((void**)&a, g_a);

    // ---- setup: dtype detect, degrees, norm, CSR build ----
    k_detect<<<1, 32>>>(ei);
    k_init_deg<<<(n + 255) / 256, 256>>>(n);
    k_count<<<(E + 255) / 256, 256>>>(ei, E);
    k_dinv<<<(n + 255) / 256, 256>>>(n);
    k_scan<<<1, 1024>>>(n);
    k_fill<<<(E + 255) / 256, 256>>>(ei, E);

    int aggBlocks = (n * 32 + 255) / 256;   // 1 warp per node

    // ---- layer 1 ----
    k_gemm<<<(n + 31) / 32, 256>>>(x, W1, h, n);
    k_agg_csr<<<aggBlocks, 256>>>(h, b1, a, n);

    // ---- layer 2 ----
    k_gemm<<<(n + 31) / 32, 256>>>(a, W2, h, n);
    k_agg_csr<<<aggBlocks, 256>>>(h, b2, out, n);
}